// round 13
// baseline (speedup 1.0000x reference)
#include <cuda_runtime.h>
#include <cuda_bf16.h>
#include <cuda_fp16.h>
#include <cstdint>

#define BB 4
#define TT 2048
#define DD 1024
#define HH 16
#define DKK 64
#define SCALE_ 0.125f
#define SC2_ 0.18033688011112042f   // 0.125 * log2(e)
#define EPS_LN_ 1e-5f
#define EPS_NORM_ 1e-8f

// within-16 perm: c -> 4*((c>>1)&3) + 2*((c>>3)&1) + (c&1)
__host__ __device__ __forceinline__ constexpr int perm16(int c) {
    return (((c >> 1) & 3) << 2) + (((c >> 3) & 1) << 1) + (c & 1);
}

// ---------------- scratch ----------------
__device__ __nv_bfloat16 g_xnh[BB * TT * DD];     // LN out bf16, D-perm16 (Q/K)
__device__ __half        g_xnf[BB * TT * DD];     // LN out fp16, D-perm16 (V)
__device__ __nv_bfloat16 g_qh[BB * HH * TT * DKK];// Q bf16, DK-perm16
__device__ __nv_bfloat16 g_kh[BB * HH * TT * DKK];// K bf16, DK-perm16
__device__ __half g_vh[BB * HH * TT * DKK];       // V fp16 [BH][T/64][DK][64 key-perm16]
__device__ __half g_aoh[BB * TT * DD];            // attn out fp16, D-perm16
__device__ __nv_bfloat16 g_wch[2 * DD * DD];      // wq, wk bf16 perm16
__device__ __half        g_wcf[2 * DD * DD];      // wv, wo fp16 perm16
__device__ unsigned char g_cmask[BB * TT];
__device__ int g_flags[3];

// ---------------- helpers ----------------
__device__ __forceinline__ void mma_bf16(float* d, const unsigned* a,
                                         const unsigned* b, const float* c) {
    asm volatile(
        "mma.sync.aligned.m16n8k16.row.col.f32.bf16.bf16.f32 "
        "{%0,%1,%2,%3}, {%4,%5,%6,%7}, {%8,%9}, {%10,%11,%12,%13};"
        : "=f"(d[0]), "=f"(d[1]), "=f"(d[2]), "=f"(d[3])
        : "r"(a[0]), "r"(a[1]), "r"(a[2]), "r"(a[3]),
          "r"(b[0]), "r"(b[1]),
          "f"(c[0]), "f"(c[1]), "f"(c[2]), "f"(c[3]));
}
__device__ __forceinline__ void mma_f16(float* d, const unsigned* a,
                                        const unsigned* b, const float* c) {
    asm volatile(
        "mma.sync.aligned.m16n8k16.row.col.f32.f16.f16.f32 "
        "{%0,%1,%2,%3}, {%4,%5,%6,%7}, {%8,%9}, {%10,%11,%12,%13};"
        : "=f"(d[0]), "=f"(d[1]), "=f"(d[2]), "=f"(d[3])
        : "r"(a[0]), "r"(a[1]), "r"(a[2]), "r"(a[3]),
          "r"(b[0]), "r"(b[1]),
          "f"(c[0]), "f"(c[1]), "f"(c[2]), "f"(c[3]));
}
__device__ __forceinline__ void cp_async16(uint32_t saddr, const void* gptr) {
    asm volatile("cp.async.cg.shared.global [%0], [%1], 16;\n" :: "r"(saddr), "l"(gptr));
}
__device__ __forceinline__ void cp_commit() { asm volatile("cp.async.commit_group;\n" ::); }
__device__ __forceinline__ void cp_wait0()  { asm volatile("cp.async.wait_group 0;\n" ::); }
__device__ __forceinline__ void cp_wait1()  { asm volatile("cp.async.wait_group 1;\n" ::); }
__device__ __forceinline__ uint32_t smem_u32(const void* p) {
    return (uint32_t)__cvta_generic_to_shared(p);
}
__device__ __forceinline__ float fexp2(float x) {
    float r;
    asm("ex2.approx.f32 %0, %1;" : "=f"(r) : "f"(x));
    return r;
}

// ---------------- mask detection / canonicalization ----------------
__global__ void detect_mask_kernel(const unsigned char* __restrict__ m) {
    if (threadIdx.x == 0) { g_flags[0] = 0; g_flags[1] = 0; g_flags[2] = 0; }
    __syncthreads();
    int a = 0, bhi = 0, c = 0;
    for (int i = threadIdx.x; i < BB * TT; i += blockDim.x) {
        unsigned char v = m[i];
        if (v) {
            int r = i & 3;
            if (r == 0) a = 1;
            else if (r == 1) c = 1;
            else bhi = 1;
        }
    }
    if (a)   atomicOr(&g_flags[0], 1);
    if (bhi) atomicOr(&g_flags[1], 1);
    if (c)   atomicOr(&g_flags[2], 1);
}
__global__ void convert_mask_kernel(const void* __restrict__ m) {
    int i = blockIdx.x * blockDim.x + threadIdx.x;
    if (i >= BB * TT) return;
    int A = g_flags[0], Bf = g_flags[1], C = g_flags[2];
    unsigned char out;
    if (A && !Bf && !C)      out = (((const int*)m)[i] != 0);
    else if (!A && Bf)       out = (((const float*)m)[i] != 0.0f);
    else                     out = (((const unsigned char*)m)[i] != 0);
    g_cmask[i] = out;
}

// ---------------- weight conversion: perm16, bf16 (q,k) / fp16 (v,o) -------
__global__ __launch_bounds__(256) void wconv_kernel(
    const float* __restrict__ w0, const float* __restrict__ w1,
    const float* __restrict__ w2, const float* __restrict__ w3) {
    int y = blockIdx.y;
    const float* src = (y == 0) ? w0 : (y == 1) ? w1 : (y == 2) ? w2 : w3;
    size_t i = ((size_t)blockIdx.x * 256 + threadIdx.x) * 4;
    float4 v = *(const float4*)&src[i];
    int r = (int)(i & 15);
    int p0 = (((r >> 1) & 3) << 2) + (((r >> 3) & 1) << 1);
    size_t b16 = i & ~(size_t)15;
    if (y < 2) {
        __nv_bfloat16* dst = g_wch + (size_t)y * DD * DD;
        *(__nv_bfloat162*)&dst[b16 + p0]     = __floats2bfloat162_rn(v.x, v.y);
        *(__nv_bfloat162*)&dst[b16 + p0 + 4] = __floats2bfloat162_rn(v.z, v.w);
    } else {
        __half* dst = g_wcf + (size_t)(y - 2) * DD * DD;
        *(__half2*)&dst[b16 + p0]     = __floats2half2_rn(v.x, v.y);
        *(__half2*)&dst[b16 + p0 + 4] = __floats2half2_rn(v.z, v.w);
    }
}

// ---------------- LayerNorm: bf16 + fp16 perm16 outputs ----------------
__global__ __launch_bounds__(256) void ln_kernel(
    const float* __restrict__ x, const float* __restrict__ g,
    const float* __restrict__ b) {
    __shared__ float red_s[8], red_ss[8];
    int row = blockIdx.x;
    int tid = threadIdx.x;
    const float* xr = x + (size_t)row * DD;
    float4 xv = *(const float4*)&xr[tid * 4];
    float s  = xv.x + xv.y + xv.z + xv.w;
    float ss = xv.x*xv.x + xv.y*xv.y + xv.z*xv.z + xv.w*xv.w;
    #pragma unroll
    for (int o = 16; o > 0; o >>= 1) {
        s  += __shfl_xor_sync(~0u, s, o);
        ss += __shfl_xor_sync(~0u, ss, o);
    }
    int warp = tid >> 5, lane = tid & 31;
    if (lane == 0) { red_s[warp] = s; red_ss[warp] = ss; }
    __syncthreads();
    if (warp == 0) {
        s  = (lane < 8) ? red_s[lane]  : 0.f;
        ss = (lane < 8) ? red_ss[lane] : 0.f;
        #pragma unroll
        for (int o = 4; o > 0; o >>= 1) {
            s  += __shfl_xor_sync(~0u, s, o);
            ss += __shfl_xor_sync(~0u, ss, o);
        }
        if (lane == 0) { red_s[0] = s; red_ss[0] = ss; }
    }
    __syncthreads();
    float mu  = red_s[0] * (1.0f / DD);
    float var = red_ss[0] * (1.0f / DD) - mu * mu;
    float inv = rsqrtf(var + EPS_LN_);
    float4 gv = *(const float4*)&g[tid * 4];
    float4 bv = *(const float4*)&b[tid * 4];
    float y0 = (xv.x - mu) * inv * gv.x + bv.x;
    float y1 = (xv.y - mu) * inv * gv.y + bv.y;
    float y2 = (xv.z - mu) * inv * gv.z + bv.z;
    float y3 = (xv.w - mu) * inv * gv.w + bv.w;
    int c0 = tid * 4;
    int r = c0 & 15;
    int p0 = (((r >> 1) & 3) << 2) + (((r >> 3) & 1) << 1);
    size_t base = (size_t)row * DD + (c0 & ~15);
    __nv_bfloat16* hd = g_xnh + base;
    *(__nv_bfloat162*)&hd[p0]     = __floats2bfloat162_rn(y0, y1);
    *(__nv_bfloat162*)&hd[p0 + 4] = __floats2bfloat162_rn(y2, y3);
    __half* fd = g_xnf + base;
    *(__half2*)&fd[p0]     = __floats2half2_rn(y0, y1);
    *(__half2*)&fd[p0 + 4] = __floats2half2_rn(y2, y3);
}

// ---------------- bf16 GEMM for Q,K: 3-stage cp.async ----------------
#define HSTR 48
#define HTILE (128 * HSTR)
#define NIT (DD / 32)
__global__ __launch_bounds__(256) void gemm_qk_kernel(
    const float* __restrict__ bq, const float* __restrict__ bk) {
    extern __shared__ __nv_bfloat16 hsm[];
    int mode = blockIdx.z;
    const __nv_bfloat16* W = g_wch + (size_t)mode * DD * DD;
    const float* bias = mode ? bk : bq;
    __nv_bfloat16* C = mode ? g_kh : g_qh;

    int tid  = threadIdx.x;
    int wid  = tid >> 5;
    int lane = tid & 31;
    int g = lane >> 2, t = lane & 3;
    int wm = (wid >> 2) * 64;
    int wn = (wid & 3) * 32;
    int m0 = blockIdx.y * 128;
    int n0 = blockIdx.x * 128;
    uint32_t sbase = smem_u32(hsm);

    float acc[4][4][4];
    #pragma unroll
    for (int i = 0; i < 4; i++)
        #pragma unroll
        for (int j = 0; j < 4; j++)
            #pragma unroll
            for (int e = 0; e < 4; e++) acc[i][j][e] = 0.f;

    auto load_stage = [&](int k0, int st) {
        #pragma unroll
        for (int p = 0; p < 2; p++) {
            int slot = tid + p * 256;
            int row  = slot >> 2;
            int col8 = (slot & 3) * 8;
            cp_async16(sbase + (uint32_t)((st * HTILE + row * HSTR + col8) * 2),
                       &g_xnh[(size_t)(m0 + row) * DD + k0 + col8]);
            cp_async16(sbase + (uint32_t)(((3 + st) * HTILE + row * HSTR + col8) * 2),
                       &W[(size_t)(n0 + row) * DD + k0 + col8]);
        }
        cp_commit();
    };

    load_stage(0, 0);
    load_stage(32, 1);
    for (int it = 0; it < NIT; it++) {
        int cur = it % 3;
        if (it + 1 < NIT) cp_wait1(); else cp_wait0();
        __syncthreads();
        if (it + 2 < NIT) load_stage((it + 2) * 32, (it + 2) % 3);
        const __nv_bfloat16* As = hsm + cur * HTILE;
        const __nv_bfloat16* Bs = hsm + (3 + cur) * HTILE;
        #pragma unroll
        for (int ks = 0; ks < 2; ks++) {
            int kc = ks * 16 + 4 * t;
            unsigned bf[4][2];
            #pragma unroll
            for (int n = 0; n < 4; n++) {
                uint2 bb = *(const uint2*)&Bs[(wn + n * 8 + g) * HSTR + kc];
                bf[n][0] = bb.x; bf[n][1] = bb.y;
            }
            #pragma unroll
            for (int mI = 0; mI < 4; mI++) {
                int rb = wm + mI * 16;
                uint2 aA = *(const uint2*)&As[(rb + g) * HSTR + kc];
                uint2 aB = *(const uint2*)&As[(rb + g + 8) * HSTR + kc];
                unsigned af[4] = {aA.x, aB.x, aA.y, aB.y};
                #pragma unroll
                for (int n = 0; n < 4; n++)
                    mma_bf16(acc[mI][n], af, bf[n], acc[mI][n]);
            }
        }
    }

    #pragma unroll
    for (int mI = 0; mI < 4; mI++) {
        int r0 = m0 + wm + mI * 16 + g;
        int bi0 = r0 >> 11, t0 = r0 & (TT - 1);
        #pragma unroll
        for (int n = 0; n < 4; n++) {
            int e = n0 + wn + n * 8 + 2 * t;
            float bb0 = bias[e], bb1 = bias[e + 1];
            float v00 = acc[mI][n][0] + bb0, v01 = acc[mI][n][1] + bb1;
            float v10 = acc[mI][n][2] + bb0, v11 = acc[mI][n][3] + bb1;
            int h = e >> 6, dk = e & 63;
            int cl = dk & 15;
            int pos = (((cl >> 1) & 3) << 2) + (((cl >> 3) & 1) << 1);
            int dkp = (dk & ~15) + pos;
            size_t base0 = (((size_t)(bi0 * HH + h) * TT + t0) << 6);
            size_t base1 = base0 + (8 << 6);
            *(__nv_bfloat162*)&C[base0 + dkp] = __floats2bfloat162_rn(v00, v01);
            *(__nv_bfloat162*)&C[base1 + dkp] = __floats2bfloat162_rn(v10, v11);
        }
    }
}

// ---------------- fp16 GEMM for V (mode 2) and O (mode 3): 3-stage ---------
__global__ __launch_bounds__(256) void gemm_vo_kernel(
    const float* __restrict__ bias, int mode, float* __restrict__ dout) {
    extern __shared__ __half fsm[];
    const __half* W = g_wcf + (size_t)(mode == 3 ? 1 : 0) * DD * DD;
    const __half* Aptr = (mode == 2) ? g_xnf : g_aoh;

    int tid  = threadIdx.x;
    int wid  = tid >> 5;
    int lane = tid & 31;
    int g = lane >> 2, t = lane & 3;
    int wm = (wid >> 2) * 64;
    int wn = (wid & 3) * 32;
    int m0 = blockIdx.y * 128;
    int n0 = blockIdx.x * 128;
    uint32_t sbase = smem_u32(fsm);

    float acc[4][4][4];
    #pragma unroll
    for (int i = 0; i < 4; i++)
        #pragma unroll
        for (int j = 0; j < 4; j++)
            #pragma unroll
            for (int e = 0; e < 4; e++) acc[i][j][e] = 0.f;

    auto load_stage = [&](int k0, int st) {
        #pragma unroll
        for (int p = 0; p < 2; p++) {
            int slot = tid + p * 256;
            int row  = slot >> 2;
            int col8 = (slot & 3) * 8;
            cp_async16(sbase + (uint32_t)((st * HTILE + row * HSTR + col8) * 2),
                       &Aptr[(size_t)(m0 + row) * DD + k0 + col8]);
            cp_async16(sbase + (uint32_t)(((3 + st) * HTILE + row * HSTR + col8) * 2),
                       &W[(size_t)(n0 + row) * DD + k0 + col8]);
        }
        cp_commit();
    };

    load_stage(0, 0);
    load_stage(32, 1);
    for (int it = 0; it < NIT; it++) {
        int cur = it % 3;
        if (it + 1 < NIT) cp_wait1(); else cp_wait0();
        __syncthreads();
        if (it + 2 < NIT) load_stage((it + 2) * 32, (it + 2) % 3);
        const __half* As = fsm + cur * HTILE;
        const __half* Bs = fsm + (3 + cur) * HTILE;
        #pragma unroll
        for (int ks = 0; ks < 2; ks++) {
            int kc = ks * 16 + 4 * t;
            unsigned bf[4][2];
            #pragma unroll
            for (int n = 0; n < 4; n++) {
                uint2 bb = *(const uint2*)&Bs[(wn + n * 8 + g) * HSTR + kc];
                bf[n][0] = bb.x; bf[n][1] = bb.y;
            }
            #pragma unroll
            for (int mI = 0; mI < 4; mI++) {
                int rb = wm + mI * 16;
                uint2 aA = *(const uint2*)&As[(rb + g) * HSTR + kc];
                uint2 aB = *(const uint2*)&As[(rb + g + 8) * HSTR + kc];
                unsigned af[4] = {aA.x, aB.x, aA.y, aB.y};
                #pragma unroll
                for (int n = 0; n < 4; n++)
                    mma_f16(acc[mI][n], af, bf[n], acc[mI][n]);
            }
        }
    }

    #pragma unroll
    for (int mI = 0; mI < 4; mI++) {
        int r0 = m0 + wm + mI * 16 + g;
        int bi0 = r0 >> 11, t0 = r0 & (TT - 1);
        #pragma unroll
        for (int n = 0; n < 4; n++) {
            int e = n0 + wn + n * 8 + 2 * t;
            float bb0 = bias[e], bb1 = bias[e + 1];
            float v00 = acc[mI][n][0] + bb0, v01 = acc[mI][n][1] + bb1;
            float v10 = acc[mI][n][2] + bb0, v11 = acc[mI][n][3] + bb1;
            if (mode == 3) {
                *(float2*)&dout[(size_t)r0 * DD + e] =
                    make_float2(v00 * 0.5f, v01 * 0.5f);
                *(float2*)&dout[(size_t)(r0 + 8) * DD + e] =
                    make_float2(v10 * 0.5f, v11 * 0.5f);
            } else {
                int h = e >> 6, dk = e & 63;
                int kt0 = t0 >> 6, ik = t0 & 63;
                int pk = (ik & ~15) | perm16(ik & 15);
                __half* vb = g_vh +
                    ((((size_t)(bi0 * HH + h) * (TT / 64) + kt0) * DKK + dk) << 6);
                vb[pk]          = __float2half_rn(v00);
                vb[64 + pk]     = __float2half_rn(v01);
                vb[pk + 2]      = __float2half_rn(v10);
                vb[64 + pk + 2] = __float2half_rn(v11);
            }
        }
    }
}

// ---------------- L2 normalize Q,K (bf16, order-invariant) ----------------
__global__ __launch_bounds__(256) void l2norm_kernel() {
    int warp = (blockIdx.x * blockDim.x + threadIdx.x) >> 5;
    int lane = threadIdx.x & 31;
    __nv_bfloat162* base =
        (__nv_bfloat162*)((blockIdx.y == 0) ? g_qh : g_kh);
    __nv_bfloat162* p = base + (size_t)warp * 32 + lane;
    float2 v = __bfloat1622float2(*p);
    float ss = v.x * v.x + v.y * v.y;
    #pragma unroll
    for (int o = 16; o > 0; o >>= 1) ss += __shfl_xor_sync(~0u, ss, o);
    float n = sqrtf(ss);
    float inv = 1.0f / fmaxf(n, EPS_NORM_);
    *p = __floats2bfloat162_rn(v.x * inv, v.y * inv);
}

// ---------------- Flash attention: 128 q/block, bf16 S, fp16 PV ----------
// Two sequential 64-row halves share every loaded K/V tile (halves K/V
// traffic + per-tile overheads). 128 threads, no reg cap -> no spills
// (persistent state ~115 regs, peak ~165; 3 CTAs/SM reg-limited).
#define KH_STR 80
#define KH_TILE_B (64 * KH_STR * 2)
#define VH_STR 80
#define VH_TILE_B (64 * VH_STR * 2)
#define VT_OFF_B (2 * KH_TILE_B)
#define P_OFF_B (VT_OFF_B + 2 * VH_TILE_B)
#define MSK_OFF_B (P_OFF_B + VH_TILE_B)
#define ASMEM (MSK_OFF_B + TT)
__global__ __launch_bounds__(128) void attn_tc_kernel() {
    extern __shared__ char asmb[];
    unsigned char* Msk = (unsigned char*)(asmb + MSK_OFF_B);
    __half* Ps = (__half*)(asmb + P_OFF_B);

    int bh = blockIdx.y;
    int bi = bh >> 4;
    int h  = bh & 15;
    int qt = blockIdx.x;                  // 128-query tile
    int tid = threadIdx.x;
    int wid = tid >> 5;
    int lane = tid & 31;
    int g = lane >> 2, t = lane & 3;
    int wg = wid * 16;
    uint32_t sbase = smem_u32(asmb);

    ((uint4*)Msk)[tid] = ((const uint4*)(g_cmask + bi * TT))[tid];

    // resident Q a-frags for both halves
    unsigned qa[2][4][4];
    #pragma unroll
    for (int hq = 0; hq < 2; hq++) {
        const __nv_bfloat16* qp0 =
            g_qh + (((size_t)(bh * TT + qt * 128 + hq * 64 + wg + g)) << 6);
        const __nv_bfloat16* qp1 = qp0 + (8 << 6);
        #pragma unroll
        for (int ks = 0; ks < 4; ks++) {
            uint2 xA = *(const uint2*)&qp0[ks * 16 + 4 * t];
            uint2 xB = *(const uint2*)&qp1[ks * 16 + 4 * t];
            qa[hq][ks][0] = xA.x; qa[hq][ks][1] = xB.x;
            qa[hq][ks][2] = xA.y; qa[hq][ks][3] = xB.y;
        }
    }

    float o_acc[2][8][4];
    #pragma unroll
    for (int hq = 0; hq < 2; hq++)
        #pragma unroll
        for (int n = 0; n < 8; n++)
            #pragma unroll
            for (int e = 0; e < 4; e++) o_acc[hq][n][e] = 0.f;
    float psum[2][2] = {{0.f, 0.f}, {0.f, 0.f}};

    const __nv_bfloat16* kbase = g_kh + (((size_t)bh * TT) << 6);
    const __half* vbase = g_vh + (((size_t)bh * TT) << 6);

    auto load_kv = [&](int kt, int st) {
        const __nv_bfloat16* kb = kbase + ((size_t)(kt * 64) << 6);
        const __half* vb = vbase + ((size_t)kt << 12);
        #pragma unroll
        for (int p = 0; p < 4; p++) {
            int slot = tid + p * 128;
            int row  = slot >> 3;
            int col8 = (slot & 7) * 8;
            cp_async16(sbase + (uint32_t)(st * KH_TILE_B + (row * KH_STR + col8) * 2),
                       &kb[(row << 6) + col8]);
        }
        #pragma unroll
        for (int p = 0; p < 4; p++) {
            int slot = tid + p * 128;
            int row  = slot >> 3;
            int col8 = (slot & 7) * 8;
            cp_async16(sbase + (uint32_t)(VT_OFF_B + st * VH_TILE_B +
                                          (row * VH_STR + col8) * 2),
                       &vb[(row << 6) + col8]);
        }
        cp_commit();
    };

    load_kv(0, 0);
    for (int kt = 0; kt < TT / 64; kt++) {
        int cur = kt & 1;
        cp_wait0();
        __syncthreads();
        if (kt < TT / 64 - 1) load_kv(kt + 1, cur ^ 1);

        const __nv_bfloat16* Ks = (const __nv_bfloat16*)(asmb + cur * KH_TILE_B);
        const __half* Vs = (const __half*)(asmb + VT_OFF_B + cur * VH_TILE_B);
        const unsigned char* mrow = Msk + kt * 64;

        #pragma unroll
        for (int hq = 0; hq < 2; hq++) {
            // S = Q.K^T (bf16)
            float sc[8][4];
            #pragma unroll
            for (int n = 0; n < 8; n++)
                #pragma unroll
                for (int e = 0; e < 4; e++) sc[n][e] = 0.f;
            #pragma unroll
            for (int ks = 0; ks < 4; ks++) {
                int kc = ks * 16 + 4 * t;
                #pragma unroll
                for (int n = 0; n < 8; n++) {
                    uint2 kb2 = *(const uint2*)&Ks[(n * 8 + g) * KH_STR + kc];
                    unsigned bf[2] = {kb2.x, kb2.y};
                    mma_bf16(sc[n], qa[hq][ks], bf, sc[n]);
                }
            }

            // static softmax via ex2; masked -> 0
            #pragma unroll
            for (int n = 0; n < 8; n++) {
                bool mk0 = mrow[n * 8 + 2 * t] != 0;
                bool mk1 = mrow[n * 8 + 2 * t + 1] != 0;
                sc[n][0] = mk0 ? 0.f : fexp2(sc[n][0] * SC2_);
                sc[n][1] = mk1 ? 0.f : fexp2(sc[n][1] * SC2_);
                sc[n][2] = mk0 ? 0.f : fexp2(sc[n][2] * SC2_);
                sc[n][3] = mk1 ? 0.f : fexp2(sc[n][3] * SC2_);
                psum[hq][0] += sc[n][0] + sc[n][1];
                psum[hq][1] += sc[n][2] + sc[n][3];
            }

            // P fp16 -> warp-private rows, key-perm16 columns
            #pragma unroll
            for (int n = 0; n < 8; n++) {
                int pc = (n >> 1) * 16 + 4 * t + 2 * (n & 1);
                *(__half2*)&Ps[(wg + g) * VH_STR + pc] =
                    __floats2half2_rn(sc[n][0], sc[n][1]);
                *(__half2*)&Ps[(wg + g + 8) * VH_STR + pc] =
                    __floats2half2_rn(sc[n][2], sc[n][3]);
            }
            __syncwarp();

            // O += P.V (fp16 m16n8k16)
            #pragma unroll
            for (int ks = 0; ks < 4; ks++) {
                int kc = ks * 16 + 4 * t;
                uint2 pA = *(const uint2*)&Ps[(wg + g) * VH_STR + kc];
                uint2 pB = *(const uint2*)&Ps[(wg + g + 8) * VH_STR + kc];
                unsigned pa[4] = {pA.x, pB.x, pA.y, pB.y};
                #pragma unroll
                for (int n = 0; n < 8; n++) {
                    uint2 vb2 = *(const uint2*)&Vs[(n * 8 + g) * VH_STR + kc];
                    unsigned bf[2] = {vb2.x, vb2.y};
                    mma_f16(o_acc[hq][n], pa, bf, o_acc[hq][n]);
                }
            }
            __syncwarp();   // P reads done before next half / next tile writes
        }
    }

    #pragma unroll
    for (int hq = 0; hq < 2; hq++) {
        float p0 = psum[hq][0], p1 = psum[hq][1];
        p0 += __shfl_xor_sync(~0u, p0, 1);
        p0 += __shfl_xor_sync(~0u, p0, 2);
        p1 += __shfl_xor_sync(~0u, p1, 1);
        p1 += __shfl_xor_sync(~0u, p1, 2);
        float inv0 = 1.0f / p0;
        float inv1 = 1.0f / p1;
        int tq0 = qt * 128 + hq * 64 + wg + g;
        __half* ob0 = g_aoh + ((size_t)bi * TT + tq0) * DD + h * 64;
        __half* ob1 = ob0 + 8 * DD;
        #pragma unroll
        for (int n = 0; n < 8; n++) {
            int pc = (n >> 1) * 16 + 4 * t + 2 * (n & 1);
            *(__half2*)&ob0[pc] =
                __floats2half2_rn(o_acc[hq][n][0] * inv0, o_acc[hq][n][1] * inv0);
            *(__half2*)&ob1[pc] =
                __floats2half2_rn(o_acc[hq][n][2] * inv1, o_acc[hq][n][3] * inv1);
        }
    }
}

// ---------------- launch ----------------
extern "C" void kernel_launch(void* const* d_in, const int* in_sizes, int n_in,
                              void* d_out, int out_size) {
    const float* x    = (const float*)d_in[0];
    const void*  mask = d_in[1];
    const float* wq = (const float*)d_in[2];
    const float* bq = (const float*)d_in[3];
    const float* wk = (const float*)d_in[4];
    const float* bk = (const float*)d_in[5];
    const float* wv = (const float*)d_in[6];
    const float* bv = (const float*)d_in[7];
    const float* wo = (const float*)d_in[8];
    const float* bo = (const float*)d_in[9];
    const float* ln_g = (const float*)d_in[10];
    const float* ln_b = (const float*)d_in[11];
    float* out = (float*)d_out;

    const int h_smem    = 6 * HTILE * 2;             // 73728 B
    const int attn_smem = ASMEM;                     // 53248 B
    cudaFuncSetAttribute(gemm_qk_kernel,
        cudaFuncAttributeMaxDynamicSharedMemorySize, h_smem);
    cudaFuncSetAttribute(gemm_vo_kernel,
        cudaFuncAttributeMaxDynamicSharedMemorySize, h_smem);
    cudaFuncSetAttribute(attn_tc_kernel,
        cudaFuncAttributeMaxDynamicSharedMemorySize, attn_smem);

    detect_mask_kernel<<<1, 256>>>((const unsigned char*)mask);
    convert_mask_kernel<<<(BB * TT + 255) / 256, 256>>>(mask);
    wconv_kernel<<<dim3(DD * DD / 1024, 4), 256>>>(wq, wk, wv, wo);
    ln_kernel<<<BB * TT, 256>>>(x, ln_g, ln_b);

    dim3 qk_grid(DD / 128, (BB * TT) / 128, 2);
    gemm_qk_kernel<<<qk_grid, 256, h_smem>>>(bq, bk);

    dim3 vgrid(DD / 128, (BB * TT) / 128);
    gemm_vo_kernel<<<vgrid, 256, h_smem>>>(bv, 2, nullptr);

    dim3 l2grid((BB * HH * TT) / 8, 2);
    l2norm_kernel<<<l2grid, 256>>>();

    dim3 agrid(TT / 128, BB * HH);                   // (16, 64)
    attn_tc_kernel<<<agrid, 128, attn_smem>>>();

    gemm_vo_kernel<<<vgrid, 256, h_smem>>>(bo, 3, out);
}

// round 14
// speedup vs baseline: 1.0030x; 1.0030x over previous
#include <cuda_runtime.h>
#include <cuda_bf16.h>
#include <cuda_fp16.h>
#include <cstdint>

#define BB 4
#define TT 2048
#define DD 1024
#define HH 16
#define DKK 64
#define SCALE_ 0.125f
#define SC2_ 0.18033688011112042f   // 0.125 * log2(e)
#define EPS_LN_ 1e-5f
#define EPS_NORM_ 1e-8f

// within-16 perm: c -> 4*((c>>1)&3) + 2*((c>>3)&1) + (c&1)
__host__ __device__ __forceinline__ constexpr int perm16(int c) {
    return (((c >> 1) & 3) << 2) + (((c >> 3) & 1) << 1) + (c & 1);
}

// ---------------- scratch ----------------
__device__ __nv_bfloat16 g_xnh[BB * TT * DD];     // LN out bf16, D-perm16 (Q/K)
__device__ __half        g_xnf[BB * TT * DD];     // LN out fp16, D-perm16 (V)
__device__ __nv_bfloat16 g_qh[BB * HH * TT * DKK];// Q bf16, DK-perm16
__device__ __nv_bfloat16 g_kh[BB * HH * TT * DKK];// K bf16, DK-perm16
__device__ __half g_vh[BB * HH * TT * DKK];       // V fp16 [BH][T/64][DK][64 key-perm16]
__device__ __half g_aoh[BB * TT * DD];            // attn out fp16, D-perm16
__device__ __nv_bfloat16 g_wch[2 * DD * DD];      // wq, wk bf16 perm16
__device__ __half        g_wcf[2 * DD * DD];      // wv, wo fp16 perm16
__device__ unsigned char g_cmask[BB * TT];
__device__ int g_flags[3];

// ---------------- helpers ----------------
__device__ __forceinline__ void mma_bf16(float* d, const unsigned* a,
                                         const unsigned* b, const float* c) {
    asm volatile(
        "mma.sync.aligned.m16n8k16.row.col.f32.bf16.bf16.f32 "
        "{%0,%1,%2,%3}, {%4,%5,%6,%7}, {%8,%9}, {%10,%11,%12,%13};"
        : "=f"(d[0]), "=f"(d[1]), "=f"(d[2]), "=f"(d[3])
        : "r"(a[0]), "r"(a[1]), "r"(a[2]), "r"(a[3]),
          "r"(b[0]), "r"(b[1]),
          "f"(c[0]), "f"(c[1]), "f"(c[2]), "f"(c[3]));
}
__device__ __forceinline__ void mma_f16(float* d, const unsigned* a,
                                        const unsigned* b, const float* c) {
    asm volatile(
        "mma.sync.aligned.m16n8k16.row.col.f32.f16.f16.f32 "
        "{%0,%1,%2,%3}, {%4,%5,%6,%7}, {%8,%9}, {%10,%11,%12,%13};"
        : "=f"(d[0]), "=f"(d[1]), "=f"(d[2]), "=f"(d[3])
        : "r"(a[0]), "r"(a[1]), "r"(a[2]), "r"(a[3]),
          "r"(b[0]), "r"(b[1]),
          "f"(c[0]), "f"(c[1]), "f"(c[2]), "f"(c[3]));
}
__device__ __forceinline__ void cp_async16(uint32_t saddr, const void* gptr) {
    asm volatile("cp.async.cg.shared.global [%0], [%1], 16;\n" :: "r"(saddr), "l"(gptr));
}
__device__ __forceinline__ void cp_commit() { asm volatile("cp.async.commit_group;\n" ::); }
__device__ __forceinline__ void cp_wait0()  { asm volatile("cp.async.wait_group 0;\n" ::); }
__device__ __forceinline__ void cp_wait1()  { asm volatile("cp.async.wait_group 1;\n" ::); }
__device__ __forceinline__ uint32_t smem_u32(const void* p) {
    return (uint32_t)__cvta_generic_to_shared(p);
}
__device__ __forceinline__ float fexp2(float x) {
    float r;
    asm("ex2.approx.f32 %0, %1;" : "=f"(r) : "f"(x));
    return r;
}

// ---------------- mask detection / canonicalization ----------------
__global__ void detect_mask_kernel(const unsigned char* __restrict__ m) {
    if (threadIdx.x == 0) { g_flags[0] = 0; g_flags[1] = 0; g_flags[2] = 0; }
    __syncthreads();
    int a = 0, bhi = 0, c = 0;
    for (int i = threadIdx.x; i < BB * TT; i += blockDim.x) {
        unsigned char v = m[i];
        if (v) {
            int r = i & 3;
            if (r == 0) a = 1;
            else if (r == 1) c = 1;
            else bhi = 1;
        }
    }
    if (a)   atomicOr(&g_flags[0], 1);
    if (bhi) atomicOr(&g_flags[1], 1);
    if (c)   atomicOr(&g_flags[2], 1);
}
__global__ void convert_mask_kernel(const void* __restrict__ m) {
    int i = blockIdx.x * blockDim.x + threadIdx.x;
    if (i >= BB * TT) return;
    int A = g_flags[0], Bf = g_flags[1], C = g_flags[2];
    unsigned char out;
    if (A && !Bf && !C)      out = (((const int*)m)[i] != 0);
    else if (!A && Bf)       out = (((const float*)m)[i] != 0.0f);
    else                     out = (((const unsigned char*)m)[i] != 0);
    g_cmask[i] = out;
}

// ---------------- weight conversion: perm16, bf16 (q,k) / fp16 (v,o) -------
__global__ __launch_bounds__(256) void wconv_kernel(
    const float* __restrict__ w0, const float* __restrict__ w1,
    const float* __restrict__ w2, const float* __restrict__ w3) {
    int y = blockIdx.y;
    const float* src = (y == 0) ? w0 : (y == 1) ? w1 : (y == 2) ? w2 : w3;
    size_t i = ((size_t)blockIdx.x * 256 + threadIdx.x) * 4;
    float4 v = *(const float4*)&src[i];
    int r = (int)(i & 15);
    int p0 = (((r >> 1) & 3) << 2) + (((r >> 3) & 1) << 1);
    size_t b16 = i & ~(size_t)15;
    if (y < 2) {
        __nv_bfloat16* dst = g_wch + (size_t)y * DD * DD;
        *(__nv_bfloat162*)&dst[b16 + p0]     = __floats2bfloat162_rn(v.x, v.y);
        *(__nv_bfloat162*)&dst[b16 + p0 + 4] = __floats2bfloat162_rn(v.z, v.w);
    } else {
        __half* dst = g_wcf + (size_t)(y - 2) * DD * DD;
        *(__half2*)&dst[b16 + p0]     = __floats2half2_rn(v.x, v.y);
        *(__half2*)&dst[b16 + p0 + 4] = __floats2half2_rn(v.z, v.w);
    }
}

// ---------------- LayerNorm: bf16 + fp16 perm16 outputs ----------------
__global__ __launch_bounds__(256) void ln_kernel(
    const float* __restrict__ x, const float* __restrict__ g,
    const float* __restrict__ b) {
    __shared__ float red_s[8], red_ss[8];
    int row = blockIdx.x;
    int tid = threadIdx.x;
    const float* xr = x + (size_t)row * DD;
    float4 xv = *(const float4*)&xr[tid * 4];
    float s  = xv.x + xv.y + xv.z + xv.w;
    float ss = xv.x*xv.x + xv.y*xv.y + xv.z*xv.z + xv.w*xv.w;
    #pragma unroll
    for (int o = 16; o > 0; o >>= 1) {
        s  += __shfl_xor_sync(~0u, s, o);
        ss += __shfl_xor_sync(~0u, ss, o);
    }
    int warp = tid >> 5, lane = tid & 31;
    if (lane == 0) { red_s[warp] = s; red_ss[warp] = ss; }
    __syncthreads();
    if (warp == 0) {
        s  = (lane < 8) ? red_s[lane]  : 0.f;
        ss = (lane < 8) ? red_ss[lane] : 0.f;
        #pragma unroll
        for (int o = 4; o > 0; o >>= 1) {
            s  += __shfl_xor_sync(~0u, s, o);
            ss += __shfl_xor_sync(~0u, ss, o);
        }
        if (lane == 0) { red_s[0] = s; red_ss[0] = ss; }
    }
    __syncthreads();
    float mu  = red_s[0] * (1.0f / DD);
    float var = red_ss[0] * (1.0f / DD) - mu * mu;
    float inv = rsqrtf(var + EPS_LN_);
    float4 gv = *(const float4*)&g[tid * 4];
    float4 bv = *(const float4*)&b[tid * 4];
    float y0 = (xv.x - mu) * inv * gv.x + bv.x;
    float y1 = (xv.y - mu) * inv * gv.y + bv.y;
    float y2 = (xv.z - mu) * inv * gv.z + bv.z;
    float y3 = (xv.w - mu) * inv * gv.w + bv.w;
    int c0 = tid * 4;
    int r = c0 & 15;
    int p0 = (((r >> 1) & 3) << 2) + (((r >> 3) & 1) << 1);
    size_t base = (size_t)row * DD + (c0 & ~15);
    __nv_bfloat16* hd = g_xnh + base;
    *(__nv_bfloat162*)&hd[p0]     = __floats2bfloat162_rn(y0, y1);
    *(__nv_bfloat162*)&hd[p0 + 4] = __floats2bfloat162_rn(y2, y3);
    __half* fd = g_xnf + base;
    *(__half2*)&fd[p0]     = __floats2half2_rn(y0, y1);
    *(__half2*)&fd[p0 + 4] = __floats2half2_rn(y2, y3);
}

// ---------------- bf16 GEMM for Q,K: 3-stage cp.async ----------------
#define HSTR 48
#define HTILE (128 * HSTR)
#define NIT (DD / 32)
__global__ __launch_bounds__(256) void gemm_qk_kernel(
    const float* __restrict__ bq, const float* __restrict__ bk) {
    extern __shared__ __nv_bfloat16 hsm[];
    int mode = blockIdx.z;
    const __nv_bfloat16* W = g_wch + (size_t)mode * DD * DD;
    const float* bias = mode ? bk : bq;
    __nv_bfloat16* C = mode ? g_kh : g_qh;

    int tid  = threadIdx.x;
    int wid  = tid >> 5;
    int lane = tid & 31;
    int g = lane >> 2, t = lane & 3;
    int wm = (wid >> 2) * 64;
    int wn = (wid & 3) * 32;
    int m0 = blockIdx.y * 128;
    int n0 = blockIdx.x * 128;
    uint32_t sbase = smem_u32(hsm);

    float acc[4][4][4];
    #pragma unroll
    for (int i = 0; i < 4; i++)
        #pragma unroll
        for (int j = 0; j < 4; j++)
            #pragma unroll
            for (int e = 0; e < 4; e++) acc[i][j][e] = 0.f;

    auto load_stage = [&](int k0, int st) {
        #pragma unroll
        for (int p = 0; p < 2; p++) {
            int slot = tid + p * 256;
            int row  = slot >> 2;
            int col8 = (slot & 3) * 8;
            cp_async16(sbase + (uint32_t)((st * HTILE + row * HSTR + col8) * 2),
                       &g_xnh[(size_t)(m0 + row) * DD + k0 + col8]);
            cp_async16(sbase + (uint32_t)(((3 + st) * HTILE + row * HSTR + col8) * 2),
                       &W[(size_t)(n0 + row) * DD + k0 + col8]);
        }
        cp_commit();
    };

    load_stage(0, 0);
    load_stage(32, 1);
    for (int it = 0; it < NIT; it++) {
        int cur = it % 3;
        if (it + 1 < NIT) cp_wait1(); else cp_wait0();
        __syncthreads();
        if (it + 2 < NIT) load_stage((it + 2) * 32, (it + 2) % 3);
        const __nv_bfloat16* As = hsm + cur * HTILE;
        const __nv_bfloat16* Bs = hsm + (3 + cur) * HTILE;
        #pragma unroll
        for (int ks = 0; ks < 2; ks++) {
            int kc = ks * 16 + 4 * t;
            unsigned bf[4][2];
            #pragma unroll
            for (int n = 0; n < 4; n++) {
                uint2 bb = *(const uint2*)&Bs[(wn + n * 8 + g) * HSTR + kc];
                bf[n][0] = bb.x; bf[n][1] = bb.y;
            }
            #pragma unroll
            for (int mI = 0; mI < 4; mI++) {
                int rb = wm + mI * 16;
                uint2 aA = *(const uint2*)&As[(rb + g) * HSTR + kc];
                uint2 aB = *(const uint2*)&As[(rb + g + 8) * HSTR + kc];
                unsigned af[4] = {aA.x, aB.x, aA.y, aB.y};
                #pragma unroll
                for (int n = 0; n < 4; n++)
                    mma_bf16(acc[mI][n], af, bf[n], acc[mI][n]);
            }
        }
    }

    #pragma unroll
    for (int mI = 0; mI < 4; mI++) {
        int r0 = m0 + wm + mI * 16 + g;
        int bi0 = r0 >> 11, t0 = r0 & (TT - 1);
        #pragma unroll
        for (int n = 0; n < 4; n++) {
            int e = n0 + wn + n * 8 + 2 * t;
            float bb0 = bias[e], bb1 = bias[e + 1];
            float v00 = acc[mI][n][0] + bb0, v01 = acc[mI][n][1] + bb1;
            float v10 = acc[mI][n][2] + bb0, v11 = acc[mI][n][3] + bb1;
            int h = e >> 6, dk = e & 63;
            int cl = dk & 15;
            int pos = (((cl >> 1) & 3) << 2) + (((cl >> 3) & 1) << 1);
            int dkp = (dk & ~15) + pos;
            size_t base0 = (((size_t)(bi0 * HH + h) * TT + t0) << 6);
            size_t base1 = base0 + (8 << 6);
            *(__nv_bfloat162*)&C[base0 + dkp] = __floats2bfloat162_rn(v00, v01);
            *(__nv_bfloat162*)&C[base1 + dkp] = __floats2bfloat162_rn(v10, v11);
        }
    }
}

// ---------------- fp16 GEMM for V (mode 2) and O (mode 3): 3-stage ---------
__global__ __launch_bounds__(256) void gemm_vo_kernel(
    const float* __restrict__ bias, int mode, float* __restrict__ dout) {
    extern __shared__ __half fsm[];
    const __half* W = g_wcf + (size_t)(mode == 3 ? 1 : 0) * DD * DD;
    const __half* Aptr = (mode == 2) ? g_xnf : g_aoh;

    int tid  = threadIdx.x;
    int wid  = tid >> 5;
    int lane = tid & 31;
    int g = lane >> 2, t = lane & 3;
    int wm = (wid >> 2) * 64;
    int wn = (wid & 3) * 32;
    int m0 = blockIdx.y * 128;
    int n0 = blockIdx.x * 128;
    uint32_t sbase = smem_u32(fsm);

    float acc[4][4][4];
    #pragma unroll
    for (int i = 0; i < 4; i++)
        #pragma unroll
        for (int j = 0; j < 4; j++)
            #pragma unroll
            for (int e = 0; e < 4; e++) acc[i][j][e] = 0.f;

    auto load_stage = [&](int k0, int st) {
        #pragma unroll
        for (int p = 0; p < 2; p++) {
            int slot = tid + p * 256;
            int row  = slot >> 2;
            int col8 = (slot & 3) * 8;
            cp_async16(sbase + (uint32_t)((st * HTILE + row * HSTR + col8) * 2),
                       &Aptr[(size_t)(m0 + row) * DD + k0 + col8]);
            cp_async16(sbase + (uint32_t)(((3 + st) * HTILE + row * HSTR + col8) * 2),
                       &W[(size_t)(n0 + row) * DD + k0 + col8]);
        }
        cp_commit();
    };

    load_stage(0, 0);
    load_stage(32, 1);
    for (int it = 0; it < NIT; it++) {
        int cur = it % 3;
        if (it + 1 < NIT) cp_wait1(); else cp_wait0();
        __syncthreads();
        if (it + 2 < NIT) load_stage((it + 2) * 32, (it + 2) % 3);
        const __half* As = fsm + cur * HTILE;
        const __half* Bs = fsm + (3 + cur) * HTILE;
        #pragma unroll
        for (int ks = 0; ks < 2; ks++) {
            int kc = ks * 16 + 4 * t;
            unsigned bf[4][2];
            #pragma unroll
            for (int n = 0; n < 4; n++) {
                uint2 bb = *(const uint2*)&Bs[(wn + n * 8 + g) * HSTR + kc];
                bf[n][0] = bb.x; bf[n][1] = bb.y;
            }
            #pragma unroll
            for (int mI = 0; mI < 4; mI++) {
                int rb = wm + mI * 16;
                uint2 aA = *(const uint2*)&As[(rb + g) * HSTR + kc];
                uint2 aB = *(const uint2*)&As[(rb + g + 8) * HSTR + kc];
                unsigned af[4] = {aA.x, aB.x, aA.y, aB.y};
                #pragma unroll
                for (int n = 0; n < 4; n++)
                    mma_f16(acc[mI][n], af, bf[n], acc[mI][n]);
            }
        }
    }

    #pragma unroll
    for (int mI = 0; mI < 4; mI++) {
        int r0 = m0 + wm + mI * 16 + g;
        int bi0 = r0 >> 11, t0 = r0 & (TT - 1);
        #pragma unroll
        for (int n = 0; n < 4; n++) {
            int e = n0 + wn + n * 8 + 2 * t;
            float bb0 = bias[e], bb1 = bias[e + 1];
            float v00 = acc[mI][n][0] + bb0, v01 = acc[mI][n][1] + bb1;
            float v10 = acc[mI][n][2] + bb0, v11 = acc[mI][n][3] + bb1;
            if (mode == 3) {
                *(float2*)&dout[(size_t)r0 * DD + e] =
                    make_float2(v00 * 0.5f, v01 * 0.5f);
                *(float2*)&dout[(size_t)(r0 + 8) * DD + e] =
                    make_float2(v10 * 0.5f, v11 * 0.5f);
            } else {
                int h = e >> 6, dk = e & 63;
                int kt0 = t0 >> 6, ik = t0 & 63;
                int pk = (ik & ~15) | perm16(ik & 15);
                __half* vb = g_vh +
                    ((((size_t)(bi0 * HH + h) * (TT / 64) + kt0) * DKK + dk) << 6);
                vb[pk]          = __float2half_rn(v00);
                vb[64 + pk]     = __float2half_rn(v01);
                vb[pk + 2]      = __float2half_rn(v10);
                vb[64 + pk + 2] = __float2half_rn(v11);
            }
        }
    }
}

// ---------------- L2 normalize Q,K (bf16, order-invariant) ----------------
__global__ __launch_bounds__(256) void l2norm_kernel() {
    int warp = (blockIdx.x * blockDim.x + threadIdx.x) >> 5;
    int lane = threadIdx.x & 31;
    __nv_bfloat162* base =
        (__nv_bfloat162*)((blockIdx.y == 0) ? g_qh : g_kh);
    __nv_bfloat162* p = base + (size_t)warp * 32 + lane;
    float2 v = __bfloat1622float2(*p);
    float ss = v.x * v.x + v.y * v.y;
    #pragma unroll
    for (int o = 16; o > 0; o >>= 1) ss += __shfl_xor_sync(~0u, ss, o);
    float n = sqrtf(ss);
    float inv = 1.0f / fmaxf(n, EPS_NORM_);
    *p = __floats2bfloat162_rn(v.x * inv, v.y * inv);
}

// ---------------- Flash attention: 128 q/block, bf16 S, fp16 PV ----------
// Two sequential 64-row halves share every loaded K/V tile (halves K/V
// traffic + per-tile overheads). 128 threads, no reg cap -> no spills
// (persistent state ~115 regs, peak ~165; 3 CTAs/SM reg-limited).
#define KH_STR 80
#define KH_TILE_B (64 * KH_STR * 2)
#define VH_STR 80
#define VH_TILE_B (64 * VH_STR * 2)
#define VT_OFF_B (2 * KH_TILE_B)
#define P_OFF_B (VT_OFF_B + 2 * VH_TILE_B)
#define MSK_OFF_B (P_OFF_B + VH_TILE_B)
#define ASMEM (MSK_OFF_B + TT)
__global__ __launch_bounds__(128) void attn_tc_kernel() {
    extern __shared__ char asmb[];
    unsigned char* Msk = (unsigned char*)(asmb + MSK_OFF_B);
    __half* Ps = (__half*)(asmb + P_OFF_B);

    int bh = blockIdx.y;
    int bi = bh >> 4;
    int h  = bh & 15;
    int qt = blockIdx.x;                  // 128-query tile
    int tid = threadIdx.x;
    int wid = tid >> 5;
    int lane = tid & 31;
    int g = lane >> 2, t = lane & 3;
    int wg = wid * 16;
    uint32_t sbase = smem_u32(asmb);

    ((uint4*)Msk)[tid] = ((const uint4*)(g_cmask + bi * TT))[tid];

    // resident Q a-frags for both halves
    unsigned qa[2][4][4];
    #pragma unroll
    for (int hq = 0; hq < 2; hq++) {
        const __nv_bfloat16* qp0 =
            g_qh + (((size_t)(bh * TT + qt * 128 + hq * 64 + wg + g)) << 6);
        const __nv_bfloat16* qp1 = qp0 + (8 << 6);
        #pragma unroll
        for (int ks = 0; ks < 4; ks++) {
            uint2 xA = *(const uint2*)&qp0[ks * 16 + 4 * t];
            uint2 xB = *(const uint2*)&qp1[ks * 16 + 4 * t];
            qa[hq][ks][0] = xA.x; qa[hq][ks][1] = xB.x;
            qa[hq][ks][2] = xA.y; qa[hq][ks][3] = xB.y;
        }
    }

    float o_acc[2][8][4];
    #pragma unroll
    for (int hq = 0; hq < 2; hq++)
        #pragma unroll
        for (int n = 0; n < 8; n++)
            #pragma unroll
            for (int e = 0; e < 4; e++) o_acc[hq][n][e] = 0.f;
    float psum[2][2] = {{0.f, 0.f}, {0.f, 0.f}};

    const __nv_bfloat16* kbase = g_kh + (((size_t)bh * TT) << 6);
    const __half* vbase = g_vh + (((size_t)bh * TT) << 6);

    auto load_kv = [&](int kt, int st) {
        const __nv_bfloat16* kb = kbase + ((size_t)(kt * 64) << 6);
        const __half* vb = vbase + ((size_t)kt << 12);
        #pragma unroll
        for (int p = 0; p < 4; p++) {
            int slot = tid + p * 128;
            int row  = slot >> 3;
            int col8 = (slot & 7) * 8;
            cp_async16(sbase + (uint32_t)(st * KH_TILE_B + (row * KH_STR + col8) * 2),
                       &kb[(row << 6) + col8]);
        }
        #pragma unroll
        for (int p = 0; p < 4; p++) {
            int slot = tid + p * 128;
            int row  = slot >> 3;
            int col8 = (slot & 7) * 8;
            cp_async16(sbase + (uint32_t)(VT_OFF_B + st * VH_TILE_B +
                                          (row * VH_STR + col8) * 2),
                       &vb[(row << 6) + col8]);
        }
        cp_commit();
    };

    load_kv(0, 0);
    for (int kt = 0; kt < TT / 64; kt++) {
        int cur = kt & 1;
        cp_wait0();
        __syncthreads();
        if (kt < TT / 64 - 1) load_kv(kt + 1, cur ^ 1);

        const __nv_bfloat16* Ks = (const __nv_bfloat16*)(asmb + cur * KH_TILE_B);
        const __half* Vs = (const __half*)(asmb + VT_OFF_B + cur * VH_TILE_B);
        const unsigned char* mrow = Msk + kt * 64;

        #pragma unroll
        for (int hq = 0; hq < 2; hq++) {
            // S = Q.K^T (bf16)
            float sc[8][4];
            #pragma unroll
            for (int n = 0; n < 8; n++)
                #pragma unroll
                for (int e = 0; e < 4; e++) sc[n][e] = 0.f;
            #pragma unroll
            for (int ks = 0; ks < 4; ks++) {
                int kc = ks * 16 + 4 * t;
                #pragma unroll
                for (int n = 0; n < 8; n++) {
                    uint2 kb2 = *(const uint2*)&Ks[(n * 8 + g) * KH_STR + kc];
                    unsigned bf[2] = {kb2.x, kb2.y};
                    mma_bf16(sc[n], qa[hq][ks], bf, sc[n]);
                }
            }

            // static softmax via ex2; masked -> 0
            #pragma unroll
            for (int n = 0; n < 8; n++) {
                bool mk0 = mrow[n * 8 + 2 * t] != 0;
                bool mk1 = mrow[n * 8 + 2 * t + 1] != 0;
                sc[n][0] = mk0 ? 0.f : fexp2(sc[n][0] * SC2_);
                sc[n][1] = mk1 ? 0.f : fexp2(sc[n][1] * SC2_);
                sc[n][2] = mk0 ? 0.f : fexp2(sc[n][2] * SC2_);
                sc[n][3] = mk1 ? 0.f : fexp2(sc[n][3] * SC2_);
                psum[hq][0] += sc[n][0] + sc[n][1];
                psum[hq][1] += sc[n][2] + sc[n][3];
            }

            // P fp16 -> warp-private rows, key-perm16 columns
            #pragma unroll
            for (int n = 0; n < 8; n++) {
                int pc = (n >> 1) * 16 + 4 * t + 2 * (n & 1);
                *(__half2*)&Ps[(wg + g) * VH_STR + pc] =
                    __floats2half2_rn(sc[n][0], sc[n][1]);
                *(__half2*)&Ps[(wg + g + 8) * VH_STR + pc] =
                    __floats2half2_rn(sc[n][2], sc[n][3]);
            }
            __syncwarp();

            // O += P.V (fp16 m16n8k16)
            #pragma unroll
            for (int ks = 0; ks < 4; ks++) {
                int kc = ks * 16 + 4 * t;
                uint2 pA = *(const uint2*)&Ps[(wg + g) * VH_STR + kc];
                uint2 pB = *(const uint2*)&Ps[(wg + g + 8) * VH_STR + kc];
                unsigned pa[4] = {pA.x, pB.x, pA.y, pB.y};
                #pragma unroll
                for (int n = 0; n < 8; n++) {
                    uint2 vb2 = *(const uint2*)&Vs[(n * 8 + g) * VH_STR + kc];
                    unsigned bf[2] = {vb2.x, vb2.y};
                    mma_f16(o_acc[hq][n], pa, bf, o_acc[hq][n]);
                }
            }
            __syncwarp();   // P reads done before next half / next tile writes
        }
    }

    #pragma unroll
    for (int hq = 0; hq < 2; hq++) {
        float p0 = psum[hq][0], p1 = psum[hq][1];
        p0 += __shfl_xor_sync(~0u, p0, 1);
        p0 += __shfl_xor_sync(~0u, p0, 2);
        p1 += __shfl_xor_sync(~0u, p1, 1);
        p1 += __shfl_xor_sync(~0u, p1, 2);
        float inv0 = 1.0f / p0;
        float inv1 = 1.0f / p1;
        int tq0 = qt * 128 + hq * 64 + wg + g;
        __half* ob0 = g_aoh + ((size_t)bi * TT + tq0) * DD + h * 64;
        __half* ob1 = ob0 + 8 * DD;
        #pragma unroll
        for (int n = 0; n < 8; n++) {
            int pc = (n >> 1) * 16 + 4 * t + 2 * (n & 1);
            *(__half2*)&ob0[pc] =
                __floats2half2_rn(o_acc[hq][n][0] * inv0, o_acc[hq][n][1] * inv0);
            *(__half2*)&ob1[pc] =
                __floats2half2_rn(o_acc[hq][n][2] * inv1, o_acc[hq][n][3] * inv1);
        }
    }
}

// ---------------- launch ----------------
extern "C" void kernel_launch(void* const* d_in, const int* in_sizes, int n_in,
                              void* d_out, int out_size) {
    const float* x    = (const float*)d_in[0];
    const void*  mask = d_in[1];
    const float* wq = (const float*)d_in[2];
    const float* bq = (const float*)d_in[3];
    const float* wk = (const float*)d_in[4];
    const float* bk = (const float*)d_in[5];
    const float* wv = (const float*)d_in[6];
    const float* bv = (const float*)d_in[7];
    const float* wo = (const float*)d_in[8];
    const float* bo = (const float*)d_in[9];
    const float* ln_g = (const float*)d_in[10];
    const float* ln_b = (const float*)d_in[11];
    float* out = (float*)d_out;

    const int h_smem    = 6 * HTILE * 2;             // 73728 B
    const int attn_smem = ASMEM;                     // 53248 B
    cudaFuncSetAttribute(gemm_qk_kernel,
        cudaFuncAttributeMaxDynamicSharedMemorySize, h_smem);
    cudaFuncSetAttribute(gemm_vo_kernel,
        cudaFuncAttributeMaxDynamicSharedMemorySize, h_smem);
    cudaFuncSetAttribute(attn_tc_kernel,
        cudaFuncAttributeMaxDynamicSharedMemorySize, attn_smem);

    detect_mask_kernel<<<1, 256>>>((const unsigned char*)mask);
    convert_mask_kernel<<<(BB * TT + 255) / 256, 256>>>(mask);
    wconv_kernel<<<dim3(DD * DD / 1024, 4), 256>>>(wq, wk, wv, wo);
    ln_kernel<<<BB * TT, 256>>>(x, ln_g, ln_b);

    dim3 qk_grid(DD / 128, (BB * TT) / 128, 2);
    gemm_qk_kernel<<<qk_grid, 256, h_smem>>>(bq, bk);

    dim3 vgrid(DD / 128, (BB * TT) / 128);
    gemm_vo_kernel<<<vgrid, 256, h_smem>>>(bv, 2, nullptr);

    dim3 l2grid((BB * HH * TT) / 8, 2);
    l2norm_kernel<<<l2grid, 256>>>();

    dim3 agrid(TT / 128, BB * HH);                   // (16, 64)
    attn_tc_kernel<<<agrid, 128, attn_smem>>>();

    gemm_vo_kernel<<<vgrid, 256, h_smem>>>(bo, 3, out);
}

// round 16
// speedup vs baseline: 1.1344x; 1.1311x over previous
#include <cuda_runtime.h>
#include <cuda_bf16.h>
#include <cuda_fp16.h>
#include <cstdint>

#define BB 4
#define TT 2048
#define DD 1024
#define HH 16
#define DKK 64
#define SCALE_ 0.125f
#define SC2_ 0.18033688011112042f   // 0.125 * log2(e)
#define EPS_LN_ 1e-5f
#define EPS_NORM_ 1e-8f

// within-16 perm: c -> 4*((c>>1)&3) + 2*((c>>3)&1) + (c&1)
__host__ __device__ __forceinline__ constexpr int perm16(int c) {
    return (((c >> 1) & 3) << 2) + (((c >> 3) & 1) << 1) + (c & 1);
}

// ---------------- scratch ----------------
__device__ __nv_bfloat16 g_xnh[BB * TT * DD];     // LN out bf16, D-perm16 (Q/K)
__device__ __half        g_xnf[BB * TT * DD];     // LN out fp16, D-perm16 (V)
__device__ __nv_bfloat16 g_qh[BB * HH * TT * DKK];// Q bf16, DK-perm16
__device__ __nv_bfloat16 g_kh[BB * HH * TT * DKK];// K bf16, DK-perm16
__device__ __half g_vh[BB * HH * TT * DKK];       // V fp16 [BH][T/64][DK][64 key-perm16]
__device__ __half g_aoh[BB * TT * DD];            // attn out fp16, D-perm16
__device__ __nv_bfloat16 g_wch[2 * DD * DD];      // wq, wk bf16 perm16
__device__ __half        g_wcf[2 * DD * DD];      // wv, wo fp16 perm16
__device__ unsigned char g_cmask[BB * TT];
__device__ int g_flags[3];

// ---------------- helpers ----------------
__device__ __forceinline__ void mma_bf16(float* d, const unsigned* a,
                                         const unsigned* b, const float* c) {
    asm volatile(
        "mma.sync.aligned.m16n8k16.row.col.f32.bf16.bf16.f32 "
        "{%0,%1,%2,%3}, {%4,%5,%6,%7}, {%8,%9}, {%10,%11,%12,%13};"
        : "=f"(d[0]), "=f"(d[1]), "=f"(d[2]), "=f"(d[3])
        : "r"(a[0]), "r"(a[1]), "r"(a[2]), "r"(a[3]),
          "r"(b[0]), "r"(b[1]),
          "f"(c[0]), "f"(c[1]), "f"(c[2]), "f"(c[3]));
}
__device__ __forceinline__ void mma_f16(float* d, const unsigned* a,
                                        const unsigned* b, const float* c) {
    asm volatile(
        "mma.sync.aligned.m16n8k16.row.col.f32.f16.f16.f32 "
        "{%0,%1,%2,%3}, {%4,%5,%6,%7}, {%8,%9}, {%10,%11,%12,%13};"
        : "=f"(d[0]), "=f"(d[1]), "=f"(d[2]), "=f"(d[3])
        : "r"(a[0]), "r"(a[1]), "r"(a[2]), "r"(a[3]),
          "r"(b[0]), "r"(b[1]),
          "f"(c[0]), "f"(c[1]), "f"(c[2]), "f"(c[3]));
}
__device__ __forceinline__ void cp_async16(uint32_t saddr, const void* gptr) {
    asm volatile("cp.async.cg.shared.global [%0], [%1], 16;\n" :: "r"(saddr), "l"(gptr));
}
__device__ __forceinline__ void cp_commit() { asm volatile("cp.async.commit_group;\n" ::); }
__device__ __forceinline__ void cp_wait0()  { asm volatile("cp.async.wait_group 0;\n" ::); }
__device__ __forceinline__ void cp_wait1()  { asm volatile("cp.async.wait_group 1;\n" ::); }
__device__ __forceinline__ uint32_t smem_u32(const void* p) {
    return (uint32_t)__cvta_generic_to_shared(p);
}
__device__ __forceinline__ float fexp2(float x) {
    float r;
    asm("ex2.approx.f32 %0, %1;" : "=f"(r) : "f"(x));
    return r;
}

// ---------------- mask detection / canonicalization ----------------
__global__ void detect_mask_kernel(const unsigned char* __restrict__ m) {
    if (threadIdx.x == 0) { g_flags[0] = 0; g_flags[1] = 0; g_flags[2] = 0; }
    __syncthreads();
    int a = 0, bhi = 0, c = 0;
    for (int i = threadIdx.x; i < BB * TT; i += blockDim.x) {
        unsigned char v = m[i];
        if (v) {
            int r = i & 3;
            if (r == 0) a = 1;
            else if (r == 1) c = 1;
            else bhi = 1;
        }
    }
    if (a)   atomicOr(&g_flags[0], 1);
    if (bhi) atomicOr(&g_flags[1], 1);
    if (c)   atomicOr(&g_flags[2], 1);
}
__global__ void convert_mask_kernel(const void* __restrict__ m) {
    int i = blockIdx.x * blockDim.x + threadIdx.x;
    if (i >= BB * TT) return;
    int A = g_flags[0], Bf = g_flags[1], C = g_flags[2];
    unsigned char out;
    if (A && !Bf && !C)      out = (((const int*)m)[i] != 0);
    else if (!A && Bf)       out = (((const float*)m)[i] != 0.0f);
    else                     out = (((const unsigned char*)m)[i] != 0);
    g_cmask[i] = out;
}

// ---------------- weight conversion: perm16, bf16 (q,k) / fp16 (v,o) -------
__global__ __launch_bounds__(256) void wconv_kernel(
    const float* __restrict__ w0, const float* __restrict__ w1,
    const float* __restrict__ w2, const float* __restrict__ w3) {
    int y = blockIdx.y;
    const float* src = (y == 0) ? w0 : (y == 1) ? w1 : (y == 2) ? w2 : w3;
    size_t i = ((size_t)blockIdx.x * 256 + threadIdx.x) * 4;
    float4 v = *(const float4*)&src[i];
    int r = (int)(i & 15);
    int p0 = (((r >> 1) & 3) << 2) + (((r >> 3) & 1) << 1);
    size_t b16 = i & ~(size_t)15;
    if (y < 2) {
        __nv_bfloat16* dst = g_wch + (size_t)y * DD * DD;
        *(__nv_bfloat162*)&dst[b16 + p0]     = __floats2bfloat162_rn(v.x, v.y);
        *(__nv_bfloat162*)&dst[b16 + p0 + 4] = __floats2bfloat162_rn(v.z, v.w);
    } else {
        __half* dst = g_wcf + (size_t)(y - 2) * DD * DD;
        *(__half2*)&dst[b16 + p0]     = __floats2half2_rn(v.x, v.y);
        *(__half2*)&dst[b16 + p0 + 4] = __floats2half2_rn(v.z, v.w);
    }
}

// ---------------- LayerNorm: bf16 + fp16 perm16 outputs ----------------
__global__ __launch_bounds__(256) void ln_kernel(
    const float* __restrict__ x, const float* __restrict__ g,
    const float* __restrict__ b) {
    __shared__ float red_s[8], red_ss[8];
    int row = blockIdx.x;
    int tid = threadIdx.x;
    const float* xr = x + (size_t)row * DD;
    float4 xv = *(const float4*)&xr[tid * 4];
    float s  = xv.x + xv.y + xv.z + xv.w;
    float ss = xv.x*xv.x + xv.y*xv.y + xv.z*xv.z + xv.w*xv.w;
    #pragma unroll
    for (int o = 16; o > 0; o >>= 1) {
        s  += __shfl_xor_sync(~0u, s, o);
        ss += __shfl_xor_sync(~0u, ss, o);
    }
    int warp = tid >> 5, lane = tid & 31;
    if (lane == 0) { red_s[warp] = s; red_ss[warp] = ss; }
    __syncthreads();
    if (warp == 0) {
        s  = (lane < 8) ? red_s[lane]  : 0.f;
        ss = (lane < 8) ? red_ss[lane] : 0.f;
        #pragma unroll
        for (int o = 4; o > 0; o >>= 1) {
            s  += __shfl_xor_sync(~0u, s, o);
            ss += __shfl_xor_sync(~0u, ss, o);
        }
        if (lane == 0) { red_s[0] = s; red_ss[0] = ss; }
    }
    __syncthreads();
    float mu  = red_s[0] * (1.0f / DD);
    float var = red_ss[0] * (1.0f / DD) - mu * mu;
    float inv = rsqrtf(var + EPS_LN_);
    float4 gv = *(const float4*)&g[tid * 4];
    float4 bv = *(const float4*)&b[tid * 4];
    float y0 = (xv.x - mu) * inv * gv.x + bv.x;
    float y1 = (xv.y - mu) * inv * gv.y + bv.y;
    float y2 = (xv.z - mu) * inv * gv.z + bv.z;
    float y3 = (xv.w - mu) * inv * gv.w + bv.w;
    int c0 = tid * 4;
    int r = c0 & 15;
    int p0 = (((r >> 1) & 3) << 2) + (((r >> 3) & 1) << 1);
    size_t base = (size_t)row * DD + (c0 & ~15);
    __nv_bfloat16* hd = g_xnh + base;
    *(__nv_bfloat162*)&hd[p0]     = __floats2bfloat162_rn(y0, y1);
    *(__nv_bfloat162*)&hd[p0 + 4] = __floats2bfloat162_rn(y2, y3);
    __half* fd = g_xnf + base;
    *(__half2*)&fd[p0]     = __floats2half2_rn(y0, y1);
    *(__half2*)&fd[p0 + 4] = __floats2half2_rn(y2, y3);
}

// ---------------- persistent fused 16-bit GEMM ----------------
// tile id: 0..511 Q (bf16), 512..1023 K (bf16), 1024..1535 V (fp16),
// 1536..2047 O (fp16). Grid-stride persistent (296 CTAs <= 2/SM concurrency)
// eliminates per-launch wave-quantization tails.
#define HSTR 48
#define HTILE (128 * HSTR)
#define NIT (DD / 32)
#define GPERS 296

template <bool IS_BF16>
__device__ __forceinline__ void gemm_mainloop(
    const char* __restrict__ Aptr, const char* __restrict__ Wptr,
    int m0, int n0, char* sm, uint32_t sbase, int tid,
    int wm, int wn, int g, int t, float acc[4][4][4]) {
    auto load_stage = [&](int k0, int st) {
        #pragma unroll
        for (int p = 0; p < 2; p++) {
            int slot = tid + p * 256;
            int row  = slot >> 2;
            int col8 = (slot & 3) * 8;
            cp_async16(sbase + (uint32_t)((st * HTILE + row * HSTR + col8) * 2),
                       Aptr + ((size_t)(m0 + row) * DD + k0 + col8) * 2);
            cp_async16(sbase + (uint32_t)(((3 + st) * HTILE + row * HSTR + col8) * 2),
                       Wptr + ((size_t)(n0 + row) * DD + k0 + col8) * 2);
        }
        cp_commit();
    };
    load_stage(0, 0);
    load_stage(32, 1);
    for (int it = 0; it < NIT; it++) {
        int cur = it % 3;
        if (it + 1 < NIT) cp_wait1(); else cp_wait0();
        __syncthreads();
        if (it + 2 < NIT) load_stage((it + 2) * 32, (it + 2) % 3);
        const __half* As = (const __half*)sm + cur * HTILE;
        const __half* Bs = (const __half*)sm + (3 + cur) * HTILE;
        #pragma unroll
        for (int ks = 0; ks < 2; ks++) {
            int kc = ks * 16 + 4 * t;
            unsigned bf[4][2];
            #pragma unroll
            for (int n = 0; n < 4; n++) {
                uint2 bb = *(const uint2*)&Bs[(wn + n * 8 + g) * HSTR + kc];
                bf[n][0] = bb.x; bf[n][1] = bb.y;
            }
            #pragma unroll
            for (int mI = 0; mI < 4; mI++) {
                int rb = wm + mI * 16;
                uint2 aA = *(const uint2*)&As[(rb + g) * HSTR + kc];
                uint2 aB = *(const uint2*)&As[(rb + g + 8) * HSTR + kc];
                unsigned af[4] = {aA.x, aB.x, aA.y, aB.y};
                #pragma unroll
                for (int n = 0; n < 4; n++) {
                    if (IS_BF16) mma_bf16(acc[mI][n], af, bf[n], acc[mI][n]);
                    else         mma_f16(acc[mI][n], af, bf[n], acc[mI][n]);
                }
            }
        }
    }
}

__global__ __launch_bounds__(256) void gemm_fused_kernel(
    const float* __restrict__ bq, const float* __restrict__ bk,
    const float* __restrict__ bv, const float* __restrict__ bo,
    float* __restrict__ dout, int tile_begin, int tile_end) {
    extern __shared__ char gsm[];
    uint32_t sbase = smem_u32(gsm);
    int tid  = threadIdx.x;
    int wid  = tid >> 5;
    int lane = tid & 31;
    int g = lane >> 2, t = lane & 3;
    int wm = (wid >> 2) * 64;
    int wn = (wid & 3) * 32;

    for (int tile = tile_begin + blockIdx.x; tile < tile_end; tile += gridDim.x) {
        int mode = tile >> 9;          // /512
        int rem  = tile & 511;
        int m0 = (rem >> 3) * 128;
        int n0 = (rem & 7) * 128;

        const char* Aptr;
        const char* Wptr;
        const float* bias;
        if (mode == 0)      { Aptr = (const char*)g_xnh; Wptr = (const char*)g_wch;                        bias = bq; }
        else if (mode == 1) { Aptr = (const char*)g_xnh; Wptr = (const char*)(g_wch + (size_t)DD * DD);    bias = bk; }
        else if (mode == 2) { Aptr = (const char*)g_xnf; Wptr = (const char*)g_wcf;                        bias = bv; }
        else                { Aptr = (const char*)g_aoh; Wptr = (const char*)(g_wcf + (size_t)DD * DD);    bias = bo; }

        float acc[4][4][4];
        #pragma unroll
        for (int i = 0; i < 4; i++)
            #pragma unroll
            for (int j = 0; j < 4; j++)
                #pragma unroll
                for (int e = 0; e < 4; e++) acc[i][j][e] = 0.f;

        if (mode < 2)
            gemm_mainloop<true>(Aptr, Wptr, m0, n0, gsm, sbase, tid, wm, wn, g, t, acc);
        else
            gemm_mainloop<false>(Aptr, Wptr, m0, n0, gsm, sbase, tid, wm, wn, g, t, acc);

        #pragma unroll
        for (int mI = 0; mI < 4; mI++) {
            int r0 = m0 + wm + mI * 16 + g;
            int bi0 = r0 >> 11, t0 = r0 & (TT - 1);
            #pragma unroll
            for (int n = 0; n < 4; n++) {
                int e = n0 + wn + n * 8 + 2 * t;
                float bb0 = bias[e], bb1 = bias[e + 1];
                float v00 = acc[mI][n][0] + bb0, v01 = acc[mI][n][1] + bb1;
                float v10 = acc[mI][n][2] + bb0, v11 = acc[mI][n][3] + bb1;
                if (mode == 3) {
                    *(float2*)&dout[(size_t)r0 * DD + e] =
                        make_float2(v00 * 0.5f, v01 * 0.5f);
                    *(float2*)&dout[(size_t)(r0 + 8) * DD + e] =
                        make_float2(v10 * 0.5f, v11 * 0.5f);
                } else if (mode == 2) {
                    int h = e >> 6, dk = e & 63;
                    int kt0 = t0 >> 6, ik = t0 & 63;
                    int pk = (ik & ~15) | perm16(ik & 15);
                    __half* vb = g_vh +
                        ((((size_t)(bi0 * HH + h) * (TT / 64) + kt0) * DKK + dk) << 6);
                    vb[pk]          = __float2half_rn(v00);
                    vb[64 + pk]     = __float2half_rn(v01);
                    vb[pk + 2]      = __float2half_rn(v10);
                    vb[64 + pk + 2] = __float2half_rn(v11);
                } else {
                    __nv_bfloat16* C = mode ? g_kh : g_qh;
                    int h = e >> 6, dk = e & 63;
                    int cl = dk & 15;
                    int dkp = (dk & ~15) + perm16(cl);
                    size_t base0 = (((size_t)(bi0 * HH + h) * TT + t0) << 6);
                    size_t base1 = base0 + (8 << 6);
                    *(__nv_bfloat162*)&C[base0 + dkp] = __floats2bfloat162_rn(v00, v01);
                    *(__nv_bfloat162*)&C[base1 + dkp] = __floats2bfloat162_rn(v10, v11);
                }
            }
        }
        __syncthreads();   // smem fully consumed before next item's loads
    }
}

// ---------------- L2 normalize Q,K (bf16, order-invariant) ----------------
__global__ __launch_bounds__(256) void l2norm_kernel() {
    int warp = (blockIdx.x * blockDim.x + threadIdx.x) >> 5;
    int lane = threadIdx.x & 31;
    __nv_bfloat162* base =
        (__nv_bfloat162*)((blockIdx.y == 0) ? g_qh : g_kh);
    __nv_bfloat162* p = base + (size_t)warp * 32 + lane;
    float2 v = __bfloat1622float2(*p);
    float ss = v.x * v.x + v.y * v.y;
    #pragma unroll
    for (int o = 16; o > 0; o >>= 1) ss += __shfl_xor_sync(~0u, ss, o);
    float n = sqrtf(ss);
    float inv = 1.0f / fmaxf(n, EPS_NORM_);
    *p = __floats2bfloat162_rn(v.x * inv, v.y * inv);
}

// ---------------- Flash attention (R12 verbatim): bf16 S, fp16 PV ---------
#define KH_STR 80
#define KH_TILE_B (64 * KH_STR * 2)
#define VH_STR 80
#define VH_TILE_B (64 * VH_STR * 2)
#define VT_OFF_B (2 * KH_TILE_B)
#define P_OFF_B (VT_OFF_B + 2 * VH_TILE_B)
#define MSK_OFF_B (P_OFF_B + VH_TILE_B)
#define ASMEM (MSK_OFF_B + TT)
__global__ __launch_bounds__(128) void attn_tc_kernel() {
    extern __shared__ char asmb[];
    unsigned char* Msk = (unsigned char*)(asmb + MSK_OFF_B);
    __half* Ps = (__half*)(asmb + P_OFF_B);

    int bh = blockIdx.y;
    int bi = bh >> 4;
    int h  = bh & 15;
    int qt = blockIdx.x;
    int tid = threadIdx.x;
    int wid = tid >> 5;
    int lane = tid & 31;
    int g = lane >> 2, t = lane & 3;
    int wg = wid * 16;
    uint32_t sbase = smem_u32(asmb);

    ((uint4*)Msk)[tid] = ((const uint4*)(g_cmask + bi * TT))[tid];

    unsigned qa[4][4];
    {
        const __nv_bfloat16* qp0 =
            g_qh + (((size_t)(bh * TT + qt * 64 + wg + g)) << 6);
        const __nv_bfloat16* qp1 = qp0 + (8 << 6);
        #pragma unroll
        for (int ks = 0; ks < 4; ks++) {
            uint2 xA = *(const uint2*)&qp0[ks * 16 + 4 * t];
            uint2 xB = *(const uint2*)&qp1[ks * 16 + 4 * t];
            qa[ks][0] = xA.x; qa[ks][1] = xB.x;
            qa[ks][2] = xA.y; qa[ks][3] = xB.y;
        }
    }

    float o_acc[8][4];
    #pragma unroll
    for (int n = 0; n < 8; n++)
        #pragma unroll
        for (int e = 0; e < 4; e++) o_acc[n][e] = 0.f;
    float psum0 = 0.f, psum1 = 0.f;

    const __nv_bfloat16* kbase = g_kh + (((size_t)bh * TT) << 6);
    const __half* vbase = g_vh + (((size_t)bh * TT) << 6);

    auto load_kv = [&](int kt, int st) {
        const __nv_bfloat16* kb = kbase + ((size_t)(kt * 64) << 6);
        const __half* vb = vbase + ((size_t)kt << 12);
        #pragma unroll
        for (int p = 0; p < 4; p++) {
            int slot = tid + p * 128;
            int row  = slot >> 3;
            int col8 = (slot & 7) * 8;
            cp_async16(sbase + (uint32_t)(st * KH_TILE_B + (row * KH_STR + col8) * 2),
                       &kb[(row << 6) + col8]);
        }
        #pragma unroll
        for (int p = 0; p < 4; p++) {
            int slot = tid + p * 128;
            int row  = slot >> 3;
            int col8 = (slot & 7) * 8;
            cp_async16(sbase + (uint32_t)(VT_OFF_B + st * VH_TILE_B +
                                          (row * VH_STR + col8) * 2),
                       &vb[(row << 6) + col8]);
        }
        cp_commit();
    };

    load_kv(0, 0);
    for (int kt = 0; kt < TT / 64; kt++) {
        int cur = kt & 1;
        cp_wait0();
        __syncthreads();
        if (kt < TT / 64 - 1) load_kv(kt + 1, cur ^ 1);

        const __nv_bfloat16* Ks = (const __nv_bfloat16*)(asmb + cur * KH_TILE_B);
        const __half* Vs = (const __half*)(asmb + VT_OFF_B + cur * VH_TILE_B);

        float sc[8][4];
        #pragma unroll
        for (int n = 0; n < 8; n++)
            #pragma unroll
            for (int e = 0; e < 4; e++) sc[n][e] = 0.f;
        #pragma unroll
        for (int ks = 0; ks < 4; ks++) {
            int kc = ks * 16 + 4 * t;
            #pragma unroll
            for (int n = 0; n < 8; n++) {
                uint2 kb2 = *(const uint2*)&Ks[(n * 8 + g) * KH_STR + kc];
                unsigned bf[2] = {kb2.x, kb2.y};
                mma_bf16(sc[n], qa[ks], bf, sc[n]);
            }
        }

        const unsigned char* mrow = Msk + kt * 64;
        #pragma unroll
        for (int n = 0; n < 8; n++) {
            bool mk0 = mrow[n * 8 + 2 * t] != 0;
            bool mk1 = mrow[n * 8 + 2 * t + 1] != 0;
            sc[n][0] = mk0 ? 0.f : fexp2(sc[n][0] * SC2_);
            sc[n][1] = mk1 ? 0.f : fexp2(sc[n][1] * SC2_);
            sc[n][2] = mk0 ? 0.f : fexp2(sc[n][2] * SC2_);
            sc[n][3] = mk1 ? 0.f : fexp2(sc[n][3] * SC2_);
            psum0 += sc[n][0] + sc[n][1];
            psum1 += sc[n][2] + sc[n][3];
        }

        #pragma unroll
        for (int n = 0; n < 8; n++) {
            int pc = (n >> 1) * 16 + 4 * t + 2 * (n & 1);
            *(__half2*)&Ps[(wg + g) * VH_STR + pc] =
                __floats2half2_rn(sc[n][0], sc[n][1]);
            *(__half2*)&Ps[(wg + g + 8) * VH_STR + pc] =
                __floats2half2_rn(sc[n][2], sc[n][3]);
        }
        __syncwarp();

        #pragma unroll
        for (int ks = 0; ks < 4; ks++) {
            int kc = ks * 16 + 4 * t;
            uint2 pA = *(const uint2*)&Ps[(wg + g) * VH_STR + kc];
            uint2 pB = *(const uint2*)&Ps[(wg + g + 8) * VH_STR + kc];
            unsigned pa[4] = {pA.x, pB.x, pA.y, pB.y};
            #pragma unroll
            for (int n = 0; n < 8; n++) {
                uint2 vb2 = *(const uint2*)&Vs[(n * 8 + g) * VH_STR + kc];
                unsigned bf[2] = {vb2.x, vb2.y};
                mma_f16(o_acc[n], pa, bf, o_acc[n]);
            }
        }
        __syncwarp();
    }

    psum0 += __shfl_xor_sync(~0u, psum0, 1);
    psum0 += __shfl_xor_sync(~0u, psum0, 2);
    psum1 += __shfl_xor_sync(~0u, psum1, 1);
    psum1 += __shfl_xor_sync(~0u, psum1, 2);
    float inv0 = 1.0f / psum0;
    float inv1 = 1.0f / psum1;
    int tq0 = qt * 64 + wg + g;
    __half* ob0 = g_aoh + ((size_t)bi * TT + tq0) * DD + h * 64;
    __half* ob1 = ob0 + 8 * DD;
    #pragma unroll
    for (int n = 0; n < 8; n++) {
        int pc = (n >> 1) * 16 + 4 * t + 2 * (n & 1);
        *(__half2*)&ob0[pc] =
            __floats2half2_rn(o_acc[n][0] * inv0, o_acc[n][1] * inv0);
        *(__half2*)&ob1[pc] =
            __floats2half2_rn(o_acc[n][2] * inv1, o_acc[n][3] * inv1);
    }
}

// ---------------- launch ----------------
extern "C" void kernel_launch(void* const* d_in, const int* in_sizes, int n_in,
                              void* d_out, int out_size) {
    const float* x    = (const float*)d_in[0];
    const void*  mask = d_in[1];
    const float* wq = (const float*)d_in[2];
    const float* bq = (const float*)d_in[3];
    const float* wk = (const float*)d_in[4];
    const float* bk = (const float*)d_in[5];
    const float* wv = (const float*)d_in[6];
    const float* bv = (const float*)d_in[7];
    const float* wo = (const float*)d_in[8];
    const float* bo = (const float*)d_in[9];
    const float* ln_g = (const float*)d_in[10];
    const float* ln_b = (const float*)d_in[11];
    float* out = (float*)d_out;

    const int h_smem    = 6 * HTILE * 2;             // 73728 B
    const int attn_smem = ASMEM;                     // 53248 B
    cudaFuncSetAttribute(gemm_fused_kernel,
        cudaFuncAttributeMaxDynamicSharedMemorySize, h_smem);
    cudaFuncSetAttribute(attn_tc_kernel,
        cudaFuncAttributeMaxDynamicSharedMemorySize, attn_smem);

    detect_mask_kernel<<<1, 256>>>((const unsigned char*)mask);
    convert_mask_kernel<<<(BB * TT + 255) / 256, 256>>>(mask);
    wconv_kernel<<<dim3(DD * DD / 1024, 4), 256>>>(wq, wk, wv, wo);
    ln_kernel<<<BB * TT, 256>>>(x, ln_g, ln_b);

    // persistent fused QKV (tiles 0..1536)
    gemm_fused_kernel<<<GPERS, 256, h_smem>>>(bq, bk, bv, bo, out, 0, 1536);

    dim3 l2grid((BB * HH * TT) / 8, 2);
    l2norm_kernel<<<l2grid, 256>>>();

    dim3 agrid(TT / 64, BB * HH);
    attn_tc_kernel<<<agrid, 128, attn_smem>>>();

    // persistent O-projection (tiles 1536..2048)
    gemm_fused_kernel<<<GPERS, 256, h_smem>>>(bq, bk, bv, bo, out, 1536, 2048);
}